// round 1
// baseline (speedup 1.0000x reference)
#include <cuda_runtime.h>

// Problem constants
#define N_ROWS   262144      // 16 * 16384 rows of z
#define D        64
#define SUBN     256
#define T_LEN    16384
#define B_DIM    16
#define ZQ_ELEMS 16777216    // 16*64*16384
#define LOSS_OFF ZQ_ELEMS
#define PERP_OFF (ZQ_ELEMS + 1)
#define IDX_OFF  (ZQ_ELEMS + 2)

#define E_STRIDE 68          // padded smem row stride (floats); 68*4=272B, 16B aligned

// Persistent device scratch (no allocation allowed)
__device__ int    g_pos;
__device__ float  g_ee[SUBN];
__device__ int    g_counts[SUBN];
__device__ double g_sse;

// ---- packed fp32x2 helpers (FFMA2: 2 fp32 FMA per issue slot) ----
__device__ __forceinline__ unsigned long long ffma2(unsigned long long a,
                                                    unsigned long long b,
                                                    unsigned long long c) {
    unsigned long long d;
    asm("fma.rn.f32x2 %0, %1, %2, %3;" : "=l"(d) : "l"(a), "l"(b), "l"(c));
    return d;
}
__device__ __forceinline__ float2 unpack2(unsigned long long v) {
    float2 r;
    asm("mov.b64 {%0, %1}, %2;" : "=f"(r.x), "=f"(r.y) : "l"(v));
    return r;
}

// ------------------------------------------------------------------
// Kernel A: pos = argmax(one_hot), ee[j] = ||E_j||^2, zero accumulators
// ------------------------------------------------------------------
__global__ void vq_prep(const float* __restrict__ one_hot,
                        const float* __restrict__ W) {
    // every thread computes pos redundantly (first-max, matches jnp.argmax)
    float m = one_hot[0];
    int p = 0;
    #pragma unroll
    for (int i = 1; i < 7; i++) {
        float v = one_hot[i];
        if (v > m) { m = v; p = i; }
    }
    int tid = threadIdx.x;      // 256 threads
    if (tid == 0) { g_pos = p; g_sse = 0.0; }

    const float* Er = W + ((size_t)p * SUBN + tid) * D;
    float s = 0.f;
    #pragma unroll
    for (int k = 0; k < D; k++) {
        float v = Er[k];
        s = fmaf(v, v, s);
    }
    g_ee[tid] = s;
    g_counts[tid] = 0;
}

// ------------------------------------------------------------------
// Kernel B: main VQ — one thread per z row, 256 rows per block
// ------------------------------------------------------------------
__global__ __launch_bounds__(256) void vq_main(const float* __restrict__ z,
                                               const float* __restrict__ W,
                                               float* __restrict__ out) {
    extern __shared__ float smem[];
    float* E_sp  = smem;                         // [256][E_STRIDE]
    float* sEE   = smem + SUBN * E_STRIDE;       // [256]
    int*   shist = (int*)(sEE + SUBN);           // [256]
    float* sred  = (float*)(shist + SUBN);       // [8]

    const int tid = threadIdx.x;
    const int pos = g_pos;

    // Load selected codebook into padded smem (coalesced float4)
    const float4* Wsrc = (const float4*)(W + (size_t)pos * SUBN * D);
    #pragma unroll 4
    for (int i = tid; i < SUBN * D / 4; i += 256) {
        int row = i >> 4;        // 16 float4 per 64-float row
        int k4  = i & 15;
        float4 v = Wsrc[i];
        *(float4*)&E_sp[row * E_STRIDE + k4 * 4] = v;
    }
    sEE[tid]   = g_ee[tid];
    shist[tid] = 0;
    __syncthreads();

    const int n = blockIdx.x * 256 + tid;        // this thread's row
    const ulonglong2* zp = (const ulonglong2*)(z + (size_t)n * D);

    // z row as 32 packed f32x2 values; ||z||^2 via packed FMA
    unsigned long long z2[32];
    unsigned long long zzacc = 0ull;
    #pragma unroll
    for (int i = 0; i < 16; i++) {
        ulonglong2 v = zp[i];
        z2[2 * i]     = v.x;
        z2[2 * i + 1] = v.y;
        zzacc = ffma2(v.x, v.x, zzacc);
        zzacc = ffma2(v.y, v.y, zzacc);
    }
    float2 zzp = unpack2(zzacc);
    float zz = zzp.x + zzp.y;

    // Argmin over 256 codes; d = (zz + ee_j) - 2*dot  (mirrors reference fp32 order)
    float best = 3.402823466e38f;
    int   bj   = 0;
    #pragma unroll 2
    for (int j = 0; j < SUBN; j++) {
        const ulonglong2* ej = (const ulonglong2*)&E_sp[j * E_STRIDE];
        unsigned long long acc0 = 0ull, acc1 = 0ull;
        #pragma unroll
        for (int i = 0; i < 16; i++) {
            ulonglong2 e = ej[i];
            acc0 = ffma2(z2[2 * i],     e.x, acc0);
            acc1 = ffma2(z2[2 * i + 1], e.y, acc1);
        }
        float2 a0 = unpack2(acc0);
        float2 a1 = unpack2(acc1);
        float dot = (a0.x + a0.y) + (a1.x + a1.y);
        float t1 = zz + sEE[j];
        float dc = t1 - 2.0f * dot;
        if (dc < best) { best = dc; bj = j; }   // strict < => first index on ties
    }

    // best == ||z - e_bj||^2  -> contributes directly to sse
    atomicAdd(&shist[bj], 1);

    // block-reduce sse
    float s = best;
    #pragma unroll
    for (int o = 16; o > 0; o >>= 1)
        s += __shfl_down_sync(0xffffffffu, s, o);
    if ((tid & 31) == 0) sred[tid >> 5] = s;
    __syncthreads();
    if (tid == 0) {
        float tot = 0.f;
        #pragma unroll
        for (int w = 0; w < 8; w++) tot += sred[w];
        atomicAdd(&g_sse, (double)tot);
    }
    // flush histogram (shist final after the syncthreads above)
    atomicAdd(&g_counts[tid], shist[tid]);

    // Write idx (as float) and transposed z_q (coalesced along t)
    out[IDX_OFF + n] = (float)bj;

    const int b = n >> 14;          // /16384
    const int t = n & (T_LEN - 1);
    float* ob = out + (size_t)b * D * T_LEN + t;
    const float* er = &E_sp[bj * E_STRIDE];
    #pragma unroll
    for (int d0 = 0; d0 < D; d0 += 4) {
        float4 v = *(const float4*)&er[d0];
        ob[(size_t)(d0 + 0) * T_LEN] = v.x;
        ob[(size_t)(d0 + 1) * T_LEN] = v.y;
        ob[(size_t)(d0 + 2) * T_LEN] = v.z;
        ob[(size_t)(d0 + 3) * T_LEN] = v.w;
    }
}

// ------------------------------------------------------------------
// Kernel C: loss + perplexity
// ------------------------------------------------------------------
__global__ void vq_finalize(float* __restrict__ out) {
    __shared__ float sw[8];
    int tid = threadIdx.x;          // 256 threads
    float c  = (float)g_counts[tid];
    float em = c * (1.0f / 262144.0f);          // exact: /2^18
    float term = em * logf(em + 1e-10f);

    float v = term;
    #pragma unroll
    for (int o = 16; o > 0; o >>= 1)
        v += __shfl_down_sync(0xffffffffu, v, o);
    if ((tid & 31) == 0) sw[tid >> 5] = v;
    __syncthreads();
    if (tid == 0) {
        float H = 0.f;
        #pragma unroll
        for (int w = 0; w < 8; w++) H += sw[w];
        out[PERP_OFF] = expf(-H);
        float m = (float)(g_sse * (1.0 / 16777216.0));
        out[LOSS_OFF] = 0.25f * m + m;          // BETA*mse + mse
    }
}

// ------------------------------------------------------------------
extern "C" void kernel_launch(void* const* d_in, const int* in_sizes, int n_in,
                              void* d_out, int out_size) {
    const float* z       = (const float*)d_in[0];
    const float* one_hot = (const float*)d_in[1];
    const float* W       = (const float*)d_in[2];
    float* out           = (float*)d_out;

    const int smem_bytes = (SUBN * E_STRIDE + SUBN) * 4 + SUBN * 4 + 8 * 4;
    cudaFuncSetAttribute(vq_main, cudaFuncAttributeMaxDynamicSharedMemorySize,
                         smem_bytes);

    vq_prep<<<1, 256>>>(one_hot, W);
    vq_main<<<N_ROWS / 256, 256, smem_bytes>>>(z, W, out);
    vq_finalize<<<1, 256>>>(out);
}